// round 10
// baseline (speedup 1.0000x reference)
#include <cuda_runtime.h>
#include <math.h>

#define L 2048
#define DIM 1024
#define NL 12
#define EX 2048
#define NS 16
#define DTRR 64
#define KC 4
#define VOCAB 50257
#define CHUNK 64
#define NCH 32
#define XPN 96
#define SPLITS 16

typedef unsigned long long ull;

__device__ __forceinline__ ull pack2(float lo, float hi){ ull r; asm("mov.b64 %0,{%1,%2};":"=l"(r):"f"(lo),"f"(hi)); return r; }
__device__ __forceinline__ void unpack2(ull v, float&a, float&b){ asm("mov.b64 {%0,%1},%2;":"=f"(a),"=f"(b):"l"(v)); }
__device__ __forceinline__ void fma2(ull&d, ull a, ull b){ asm("fma.rn.f32x2 %0,%1,%2,%0;":"+l"(d):"l"(a),"l"(b)); }

__device__ __forceinline__ float silu_f(float x){ return x/(1.f+__expf(-x)); }
__device__ __forceinline__ float softplus_f(float x){ return fmaxf(x,0.f)+log1pf(__expf(-fabsf(x))); }

// ---------------- scratch (static device memory; no allocs) ----------------
#define SZ_MAT (L*DIM)
#define SZ_XZ  (L*2*EX)
#define SZ_E   (L*EX)
#define SZ_DBC (L*XPN)
#define SZ_PF  (NCH*EX*NS)

#define O_RES 0
#define O_H   (O_RES+SZ_MAT)
#define O_X   (O_H+SZ_MAT)
#define O_XZ  (O_X+SZ_MAT)
#define O_XC  (O_XZ+SZ_XZ)
#define O_DT  (O_XC+SZ_E)
#define O_Y   (O_DT+SZ_E)
#define O_DBC (O_Y+SZ_E)
#define O_P   (O_DBC+SZ_DBC)
#define O_F   (O_P+SZ_PF)
#define O_HIN (O_F+SZ_PF)
#define O_XPP (O_HIN+SZ_PF)
#define SCRATCH_TOTAL (O_XPP + SPLITS*SZ_DBC)

__device__ __align__(256) float g_scr[SCRATCH_TOTAL];

// ---------------- generic GEMM: C[M,N] = A[M,K] * B[N,K]^T ----------------
// 128x128 block tile, BK=8, 256 threads, 8x8 micro-tile, f32x2 packed FMA.
// Grid: (M/128, ceil(N/128), splits). Split-K writes disjoint partial buffers
// (C + z*partStride) for determinism; EPI=2 fuses bias + softplus.
template<int EPI>
__global__ __launch_bounds__(256,2)
void gemm_tn(const float* __restrict__ A, int lda,
             const float* __restrict__ B, int ldb,
             float* __restrict__ C, int ldc, int partStride,
             int N, int kLen, const float* __restrict__ bias)
{
    __shared__ float As[8][128];
    __shared__ float Bs[8][128];
    const int bm = blockIdx.x*128;
    const int bn = blockIdx.y*128;
    const int k0 = blockIdx.z*kLen;
    const int tid = threadIdx.x;
    const int tx = tid & 15, ty = tid >> 4;
    const int lrow = tid >> 1;
    const int lkq = (tid & 1) << 2;

    const float* Ap = A + (size_t)(bm+lrow)*lda + k0 + lkq;
    const bool bval = (bn+lrow) < N;
    const float* Bp = B + (size_t)(bval ? (bn+lrow) : 0)*ldb + k0 + lkq;

    ull acc[8][4];
#pragma unroll
    for (int m=0;m<8;m++)
#pragma unroll
        for (int j=0;j<4;j++) acc[m][j]=0ull;

    float4 av = *(const float4*)Ap;
    float4 bv = bval ? *(const float4*)Bp : make_float4(0.f,0.f,0.f,0.f);

    for (int kt=0; kt<kLen; kt+=8){
        __syncthreads();
        As[lkq+0][lrow]=av.x; As[lkq+1][lrow]=av.y; As[lkq+2][lrow]=av.z; As[lkq+3][lrow]=av.w;
        Bs[lkq+0][lrow]=bv.x; Bs[lkq+1][lrow]=bv.y; Bs[lkq+2][lrow]=bv.z; Bs[lkq+3][lrow]=bv.w;
        __syncthreads();
        if (kt+8 < kLen){
            av = *(const float4*)(Ap+kt+8);
            bv = bval ? *(const float4*)(Bp+kt+8) : make_float4(0.f,0.f,0.f,0.f);
        }
#pragma unroll
        for (int kk=0;kk<8;kk++){
            float4 a0 = *(const float4*)&As[kk][ty*8];
            float4 a1 = *(const float4*)&As[kk][ty*8+4];
            float4 b0 = *(const float4*)&Bs[kk][tx*8];
            float4 b1 = *(const float4*)&Bs[kk][tx*8+4];
            ull bp0=pack2(b0.x,b0.y), bp1=pack2(b0.z,b0.w);
            ull bp2=pack2(b1.x,b1.y), bp3=pack2(b1.z,b1.w);
            float am[8]={a0.x,a0.y,a0.z,a0.w,a1.x,a1.y,a1.z,a1.w};
#pragma unroll
            for (int m=0;m<8;m++){
                ull ap = pack2(am[m],am[m]);
                fma2(acc[m][0],ap,bp0); fma2(acc[m][1],ap,bp1);
                fma2(acc[m][2],ap,bp2); fma2(acc[m][3],ap,bp3);
            }
        }
    }
    float* Cz = C + (size_t)blockIdx.z*partStride;
#pragma unroll
    for (int m=0;m<8;m++){
        int gm = bm + ty*8 + m;
        float* Crow = Cz + (size_t)gm*ldc;
#pragma unroll
        for (int j=0;j<4;j++){
            float v0,v1; unpack2(acc[m][j],v0,v1);
            int gn = bn + tx*8 + j*2;
            if (EPI==0){
                if (gn   < N) Crow[gn]   = v0;
                if (gn+1 < N) Crow[gn+1] = v1;
            } else {
                if (gn   < N) Crow[gn]   = softplus_f(v0+bias[gn]);
                if (gn+1 < N) Crow[gn+1] = softplus_f(v1+bias[gn+1]);
            }
        }
    }
}

// ---------------- embedding gather ----------------
__global__ void embed_k(const int* __restrict__ ids, const float* __restrict__ emb, float* __restrict__ res){
    int i = blockIdx.x*256 + threadIdx.x;
    int l = i >> 10;
    res[i] = emb[(size_t)ids[l]*DIM + (i & (DIM-1))];
}

// ---------------- residual add + RMSNorm (one row per block) ----------------
__global__ void addnorm_k(float* __restrict__ res, const float* __restrict__ xin,
                          const float* __restrict__ w, float* __restrict__ hout, int addX){
    int r = blockIdx.x;
    float* rr = res + (size_t)r*DIM;
    const float* xr = xin + (size_t)r*DIM;
    float v[4]; float s=0.f;
#pragma unroll
    for (int q=0;q<4;q++){
        int j = threadIdx.x + q*256;
        float val = rr[j];
        if (addX){ val += xr[j]; rr[j]=val; }
        v[q]=val; s += val*val;
    }
#pragma unroll
    for (int o=16;o>0;o>>=1) s += __shfl_xor_sync(0xffffffffu, s, o);
    __shared__ float red[8];
    if ((threadIdx.x&31)==0) red[threadIdx.x>>5]=s;
    __syncthreads();
    if (threadIdx.x<32){
        float t = (threadIdx.x<8)?red[threadIdx.x]:0.f;
#pragma unroll
        for (int o=4;o>0;o>>=1) t += __shfl_xor_sync(0xffffffffu,t,o);
        if (threadIdx.x==0) red[0] = rsqrtf(t/(float)DIM + 1e-5f);
    }
    __syncthreads();
    float inv = red[0];
#pragma unroll
    for (int q=0;q<4;q++){
        int j = threadIdx.x + q*256;
        hout[(size_t)r*DIM+j] = v[q]*inv*w[j];
    }
}

// ---------------- causal depthwise conv (K=4) + SiLU ----------------
__global__ void conv_silu_k(const float* __restrict__ xz, const float* __restrict__ cw,
                            const float* __restrict__ cb, float* __restrict__ xc){
    int i = blockIdx.x*256+threadIdx.x;   // i = l*EX + e
    int e = i & (EX-1);
    int l = i >> 11;
    float4 w = *(const float4*)(cw + e*4);
    const float* col = xz + e;
    float s = cb[e] + w.w*col[(size_t)l*(2*EX)];
    if (l>=1) s += w.z*col[(size_t)(l-1)*(2*EX)];
    if (l>=2) s += w.y*col[(size_t)(l-2)*(2*EX)];
    if (l>=3) s += w.x*col[(size_t)(l-3)*(2*EX)];
    xc[i] = silu_f(s);
}

// ---------------- split-K reduction for x_proj partials ----------------
__global__ void reduce16_k(const float* __restrict__ part, float* __restrict__ outp){
    int i = blockIdx.x*256+threadIdx.x;
    float s=0.f;
#pragma unroll
    for (int z=0;z<SPLITS;z++) s += part[(size_t)z*SZ_DBC + i];
    outp[i]=s;
}

// ---------------- selective scan: chunked 3-phase ----------------
// Phase A: per (chunk,e) local scan from h=0 -> products P and local finals F.
__global__ __launch_bounds__(256)
void scanA_k(const float* __restrict__ dt, const float* __restrict__ xc, const float* __restrict__ dbc,
             const float* __restrict__ Alog, float* __restrict__ P, float* __restrict__ F){
    int e = blockIdx.x*256 + threadIdx.x;
    int c = blockIdx.y;
    __shared__ float Bsh[CHUNK][NS];
    for (int idx=threadIdx.x; idx<CHUNK*NS; idx+=256){
        int tt = idx>>4, n = idx&15;
        Bsh[tt][n] = dbc[(size_t)(c*CHUNK+tt)*XPN + DTRR + n];
    }
    __syncthreads();
    float Aa[NS], h[NS], p[NS];
#pragma unroll
    for (int n=0;n<NS;n++){ Aa[n] = -__expf(Alog[(size_t)e*NS+n]); h[n]=0.f; p[n]=1.f; }
    int t0=c*CHUNK;
    for (int tt=0;tt<CHUNK;tt++){
        int t=t0+tt;
        float dtv = dt[(size_t)t*EX+e];
        float du  = dtv*xc[(size_t)t*EX+e];
#pragma unroll
        for (int n=0;n<NS;n++){
            float dA = __expf(dtv*Aa[n]);
            h[n] = dA*h[n] + du*Bsh[tt][n];
            p[n]*= dA;
        }
    }
    size_t bse = ((size_t)c*EX + e)*NS;
#pragma unroll
    for (int n=0;n<NS;n++){ P[bse+n]=p[n]; F[bse+n]=h[n]; }
}

// Phase B: sequential combine over the 32 chunks (per (e,n) thread).
__global__ void scanB_k(const float* __restrict__ P, const float* __restrict__ F, float* __restrict__ Hin){
    int idx = blockIdx.x*256+threadIdx.x;
    float h=0.f;
    for (int c=0;c<NCH;c++){
        size_t o = (size_t)c*(EX*NS) + idx;
        Hin[o]=h;
        h = P[o]*h + F[o];
    }
}

// Phase C: replay with true initial state; emit y = (h.C + D*xc)*silu(z).
__global__ __launch_bounds__(256)
void scanC_k(const float* __restrict__ dt, const float* __restrict__ xc, const float* __restrict__ dbc,
             const float* __restrict__ Alog, const float* __restrict__ Hin,
             const float* __restrict__ Dp, const float* __restrict__ xz, float* __restrict__ y){
    int e = blockIdx.x*256 + threadIdx.x;
    int c = blockIdx.y;
    __shared__ float Bsh[CHUNK][NS];
    __shared__ float Csh[CHUNK][NS];
    for (int idx=threadIdx.x; idx<CHUNK*NS; idx+=256){
        int tt = idx>>4, n = idx&15;
        const float* row = dbc + (size_t)(c*CHUNK+tt)*XPN;
        Bsh[tt][n] = row[DTRR+n];
        Csh[tt][n] = row[DTRR+NS+n];
    }
    __syncthreads();
    float Aa[NS], h[NS];
    size_t hb = ((size_t)c*EX+e)*NS;
#pragma unroll
    for (int n=0;n<NS;n++){ Aa[n]=-__expf(Alog[(size_t)e*NS+n]); h[n]=Hin[hb+n]; }
    float Dv = Dp[e];
    int t0=c*CHUNK;
    for (int tt=0;tt<CHUNK;tt++){
        int t=t0+tt;
        float dtv = dt[(size_t)t*EX+e];
        float xcv = xc[(size_t)t*EX+e];
        float du = dtv*xcv;
        float acc=0.f;
#pragma unroll
        for (int n=0;n<NS;n++){
            float dA=__expf(dtv*Aa[n]);
            h[n]=dA*h[n]+du*Bsh[tt][n];
            acc += h[n]*Csh[tt][n];
        }
        float z = xz[(size_t)t*(2*EX) + EX + e];
        y[(size_t)t*EX+e] = (acc + Dv*xcv)*silu_f(z);
    }
}

// ---------------- orchestration ----------------
extern "C" void kernel_launch(void* const* d_in, const int* in_sizes, int n_in,
                              void* d_out, int out_size) {
    const int*   ids  = (const int*)d_in[0];
    const float* emb  = (const float*)d_in[1];
    const float* inw  = (const float*)d_in[2];
    const float* cw   = (const float*)d_in[3];
    const float* cb   = (const float*)d_in[4];
    const float* xpw  = (const float*)d_in[5];
    const float* dtw  = (const float*)d_in[6];
    const float* dtb  = (const float*)d_in[7];
    const float* alog = (const float*)d_in[8];
    const float* dpar = (const float*)d_in[9];
    const float* outw = (const float*)d_in[10];
    const float* nw   = (const float*)d_in[11];
    const float* nfw  = (const float*)d_in[12];
    const float* hw   = (const float*)d_in[13];
    float* out = (float*)d_out;

    float* base = nullptr;
    cudaGetSymbolAddress((void**)&base, g_scr);
    float* p_res = base+O_RES; float* p_h   = base+O_H;   float* p_x   = base+O_X;
    float* p_xz  = base+O_XZ;  float* p_xc  = base+O_XC;  float* p_dt  = base+O_DT;
    float* p_y   = base+O_Y;   float* p_dbc = base+O_DBC; float* p_P   = base+O_P;
    float* p_F   = base+O_F;   float* p_hin = base+O_HIN; float* p_xpp = base+O_XPP;

    embed_k<<<(L*DIM)/256,256>>>(ids, emb, p_res);

    for (int i=0;i<NL;i++){
        // residual add (skipped layer 0) + rmsnorm -> h
        addnorm_k<<<L,256>>>(p_res, p_x, nw + (size_t)i*DIM, p_h, i>0);
        // xz = h @ in_proj^T   (2048 x 4096 x 1024)
        gemm_tn<0><<<dim3(L/128, (2*EX)/128, 1),256>>>(p_h, DIM, inw + (size_t)i*2*EX*DIM, DIM,
                                                       p_xz, 2*EX, 0, 2*EX, DIM, nullptr);
        // causal depthwise conv + silu on x-half of xz -> xc
        conv_silu_k<<<(L*EX)/256,256>>>(p_xz, cw + (size_t)i*EX*KC, cb + (size_t)i*EX, p_xc);
        // dbc = xc @ x_proj^T  (2048 x 96 x 2048), split-K into partials, then reduce
        gemm_tn<0><<<dim3(L/128, 1, SPLITS),256>>>(p_xc, EX, xpw + (size_t)i*XPN*EX, EX,
                                                   p_xpp, XPN, SZ_DBC, XPN, EX/SPLITS, nullptr);
        reduce16_k<<<SZ_DBC/256,256>>>(p_xpp, p_dbc);
        // dt = softplus(dbc[:, :64] @ dt_proj^T + dt_b)  (2048 x 2048 x 64)
        gemm_tn<2><<<dim3(L/128, EX/128, 1),256>>>(p_dbc, XPN, dtw + (size_t)i*EX*DTRR, DTRR,
                                                   p_dt, EX, 0, EX, DTRR, dtb + (size_t)i*EX);
        // chunked selective scan + z-gating -> y
        scanA_k<<<dim3(EX/256, NCH),256>>>(p_dt, p_xc, p_dbc, alog + (size_t)i*EX*NS, p_P, p_F);
        scanB_k<<<(EX*NS)/256,256>>>(p_P, p_F, p_hin);
        scanC_k<<<dim3(EX/256, NCH),256>>>(p_dt, p_xc, p_dbc, alog + (size_t)i*EX*NS,
                                           p_hin, dpar + (size_t)i*EX, p_xz, p_y);
        // x = y @ out_proj^T   (2048 x 1024 x 2048)
        gemm_tn<0><<<dim3(L/128, DIM/128, 1),256>>>(p_y, EX, outw + (size_t)i*DIM*EX, EX,
                                                    p_x, DIM, 0, DIM, EX, nullptr);
    }

    // final residual + rmsnorm, then LM head (2048 x 50257 x 1024)
    addnorm_k<<<L,256>>>(p_res, p_x, nfw, p_h, 1);
    gemm_tn<0><<<dim3(L/128, (VOCAB+127)/128, 1),256>>>(p_h, DIM, hw, DIM,
                                                        out, VOCAB, 0, VOCAB, DIM, nullptr);
}

// round 11
// speedup vs baseline: 1.0018x; 1.0018x over previous
#include <cuda_runtime.h>
#include <math.h>

#define L 2048
#define DIM 1024
#define NL 12
#define EX 2048
#define NS 16
#define DTRR 64
#define KC 4
#define VOCAB 50257
#define CHUNK 64
#define NCH 32
#define XPN 96
#define SPLITS 16

typedef unsigned long long ull;

__device__ __forceinline__ ull pack2(float lo, float hi){ ull r; asm("mov.b64 %0,{%1,%2};":"=l"(r):"f"(lo),"f"(hi)); return r; }
__device__ __forceinline__ void unpack2(ull v, float&a, float&b){ asm("mov.b64 {%0,%1},%2;":"=f"(a),"=f"(b):"l"(v)); }
__device__ __forceinline__ void fma2(ull&d, ull a, ull b){ asm("fma.rn.f32x2 %0,%1,%2,%0;":"+l"(d):"l"(a),"l"(b)); }

__device__ __forceinline__ float silu_f(float x){ return x/(1.f+__expf(-x)); }
__device__ __forceinline__ float softplus_f(float x){ return fmaxf(x,0.f)+log1pf(__expf(-fabsf(x))); }

// ---------------- scratch (static device memory; no allocs) ----------------
#define SZ_MAT (L*DIM)
#define SZ_XZ  (L*2*EX)
#define SZ_E   (L*EX)
#define SZ_DBC (L*XPN)
#define SZ_PF  (NCH*EX*NS)

#define O_RES 0
#define O_H   (O_RES+SZ_MAT)
#define O_X   (O_H+SZ_MAT)
#define O_XZ  (O_X+SZ_MAT)
#define O_XC  (O_XZ+SZ_XZ)
#define O_DT  (O_XC+SZ_E)
#define O_Y   (O_DT+SZ_E)
#define O_DBC (O_Y+SZ_E)
#define O_P   (O_DBC+SZ_DBC)
#define O_F   (O_P+SZ_PF)
#define O_HIN (O_F+SZ_PF)
#define O_XPP (O_HIN+SZ_PF)
#define SCRATCH_TOTAL (O_XPP + SPLITS*SZ_DBC)

__device__ __align__(256) float g_scr[SCRATCH_TOTAL];

// ---------------- generic GEMM: C[M,N] = A[M,K] * B[N,K]^T ----------------
// 128x128 block tile, BK=8, 256 threads, 8x8 micro-tile, f32x2 packed FMA.
// Grid: (M/128, ceil(N/128), splits). Split-K writes disjoint partial buffers
// (C + z*partStride) for determinism; EPI=2 fuses bias + softplus.
template<int EPI>
__global__ __launch_bounds__(256,2)
void gemm_tn(const float* __restrict__ A, int lda,
             const float* __restrict__ B, int ldb,
             float* __restrict__ C, int ldc, int partStride,
             int N, int kLen, const float* __restrict__ bias)
{
    __shared__ float As[8][128];
    __shared__ float Bs[8][128];
    const int bm = blockIdx.x*128;
    const int bn = blockIdx.y*128;
    const int k0 = blockIdx.z*kLen;
    const int tid = threadIdx.x;
    const int tx = tid & 15, ty = tid >> 4;
    const int lrow = tid >> 1;
    const int lkq = (tid & 1) << 2;

    const float* Ap = A + (size_t)(bm+lrow)*lda + k0 + lkq;
    const bool bval = (bn+lrow) < N;
    const float* Bp = B + (size_t)(bval ? (bn+lrow) : 0)*ldb + k0 + lkq;

    ull acc[8][4];
#pragma unroll
    for (int m=0;m<8;m++)
#pragma unroll
        for (int j=0;j<4;j++) acc[m][j]=0ull;

    float4 av = *(const float4*)Ap;
    float4 bv = bval ? *(const float4*)Bp : make_float4(0.f,0.f,0.f,0.f);

    for (int kt=0; kt<kLen; kt+=8){
        __syncthreads();
        As[lkq+0][lrow]=av.x; As[lkq+1][lrow]=av.y; As[lkq+2][lrow]=av.z; As[lkq+3][lrow]=av.w;
        Bs[lkq+0][lrow]=bv.x; Bs[lkq+1][lrow]=bv.y; Bs[lkq+2][lrow]=bv.z; Bs[lkq+3][lrow]=bv.w;
        __syncthreads();
        if (kt+8 < kLen){
            av = *(const float4*)(Ap+kt+8);
            bv = bval ? *(const float4*)(Bp+kt+8) : make_float4(0.f,0.f,0.f,0.f);
        }
#pragma unroll
        for (int kk=0;kk<8;kk++){
            float4 a0 = *(const float4*)&As[kk][ty*8];
            float4 a1 = *(const float4*)&As[kk][ty*8+4];
            float4 b0 = *(const float4*)&Bs[kk][tx*8];
            float4 b1 = *(const float4*)&Bs[kk][tx*8+4];
            ull bp0=pack2(b0.x,b0.y), bp1=pack2(b0.z,b0.w);
            ull bp2=pack2(b1.x,b1.y), bp3=pack2(b1.z,b1.w);
            float am[8]={a0.x,a0.y,a0.z,a0.w,a1.x,a1.y,a1.z,a1.w};
#pragma unroll
            for (int m=0;m<8;m++){
                ull ap = pack2(am[m],am[m]);
                fma2(acc[m][0],ap,bp0); fma2(acc[m][1],ap,bp1);
                fma2(acc[m][2],ap,bp2); fma2(acc[m][3],ap,bp3);
            }
        }
    }
    float* Cz = C + (size_t)blockIdx.z*partStride;
#pragma unroll
    for (int m=0;m<8;m++){
        int gm = bm + ty*8 + m;
        float* Crow = Cz + (size_t)gm*ldc;
#pragma unroll
        for (int j=0;j<4;j++){
            float v0,v1; unpack2(acc[m][j],v0,v1);
            int gn = bn + tx*8 + j*2;
            if (EPI==0){
                if (gn   < N) Crow[gn]   = v0;
                if (gn+1 < N) Crow[gn+1] = v1;
            } else {
                if (gn   < N) Crow[gn]   = softplus_f(v0+bias[gn]);
                if (gn+1 < N) Crow[gn+1] = softplus_f(v1+bias[gn+1]);
            }
        }
    }
}

// ---------------- embedding gather ----------------
__global__ void embed_k(const int* __restrict__ ids, const float* __restrict__ emb, float* __restrict__ res){
    int i = blockIdx.x*256 + threadIdx.x;
    int l = i >> 10;
    res[i] = emb[(size_t)ids[l]*DIM + (i & (DIM-1))];
}

// ---------------- residual add + RMSNorm (one row per block) ----------------
__global__ void addnorm_k(float* __restrict__ res, const float* __restrict__ xin,
                          const float* __restrict__ w, float* __restrict__ hout, int addX){
    int r = blockIdx.x;
    float* rr = res + (size_t)r*DIM;
    const float* xr = xin + (size_t)r*DIM;
    float v[4]; float s=0.f;
#pragma unroll
    for (int q=0;q<4;q++){
        int j = threadIdx.x + q*256;
        float val = rr[j];
        if (addX){ val += xr[j]; rr[j]=val; }
        v[q]=val; s += val*val;
    }
#pragma unroll
    for (int o=16;o>0;o>>=1) s += __shfl_xor_sync(0xffffffffu, s, o);
    __shared__ float red[8];
    if ((threadIdx.x&31)==0) red[threadIdx.x>>5]=s;
    __syncthreads();
    if (threadIdx.x<32){
        float t = (threadIdx.x<8)?red[threadIdx.x]:0.f;
#pragma unroll
        for (int o=4;o>0;o>>=1) t += __shfl_xor_sync(0xffffffffu,t,o);
        if (threadIdx.x==0) red[0] = rsqrtf(t/(float)DIM + 1e-5f);
    }
    __syncthreads();
    float inv = red[0];
#pragma unroll
    for (int q=0;q<4;q++){
        int j = threadIdx.x + q*256;
        hout[(size_t)r*DIM+j] = v[q]*inv*w[j];
    }
}

// ---------------- causal depthwise conv (K=4) + SiLU ----------------
__global__ void conv_silu_k(const float* __restrict__ xz, const float* __restrict__ cw,
                            const float* __restrict__ cb, float* __restrict__ xc){
    int i = blockIdx.x*256+threadIdx.x;   // i = l*EX + e
    int e = i & (EX-1);
    int l = i >> 11;
    float4 w = *(const float4*)(cw + e*4);
    const float* col = xz + e;
    float s = cb[e] + w.w*col[(size_t)l*(2*EX)];
    if (l>=1) s += w.z*col[(size_t)(l-1)*(2*EX)];
    if (l>=2) s += w.y*col[(size_t)(l-2)*(2*EX)];
    if (l>=3) s += w.x*col[(size_t)(l-3)*(2*EX)];
    xc[i] = silu_f(s);
}

// ---------------- split-K reduction for x_proj partials ----------------
__global__ void reduce16_k(const float* __restrict__ part, float* __restrict__ outp){
    int i = blockIdx.x*256+threadIdx.x;
    float s=0.f;
#pragma unroll
    for (int z=0;z<SPLITS;z++) s += part[(size_t)z*SZ_DBC + i];
    outp[i]=s;
}

// ---------------- selective scan: chunked 3-phase ----------------
// Phase A: per (chunk,e) local scan from h=0 -> products P and local finals F.
__global__ __launch_bounds__(256)
void scanA_k(const float* __restrict__ dt, const float* __restrict__ xc, const float* __restrict__ dbc,
             const float* __restrict__ Alog, float* __restrict__ P, float* __restrict__ F){
    int e = blockIdx.x*256 + threadIdx.x;
    int c = blockIdx.y;
    __shared__ float Bsh[CHUNK][NS];
    for (int idx=threadIdx.x; idx<CHUNK*NS; idx+=256){
        int tt = idx>>4, n = idx&15;
        Bsh[tt][n] = dbc[(size_t)(c*CHUNK+tt)*XPN + DTRR + n];
    }
    __syncthreads();
    float Aa[NS], h[NS], p[NS];
#pragma unroll
    for (int n=0;n<NS;n++){ Aa[n] = -__expf(Alog[(size_t)e*NS+n]); h[n]=0.f; p[n]=1.f; }
    int t0=c*CHUNK;
    for (int tt=0;tt<CHUNK;tt++){
        int t=t0+tt;
        float dtv = dt[(size_t)t*EX+e];
        float du  = dtv*xc[(size_t)t*EX+e];
#pragma unroll
        for (int n=0;n<NS;n++){
            float dA = __expf(dtv*Aa[n]);
            h[n] = dA*h[n] + du*Bsh[tt][n];
            p[n]*= dA;
        }
    }
    size_t bse = ((size_t)c*EX + e)*NS;
#pragma unroll
    for (int n=0;n<NS;n++){ P[bse+n]=p[n]; F[bse+n]=h[n]; }
}

// Phase B: sequential combine over the 32 chunks (per (e,n) thread).
__global__ void scanB_k(const float* __restrict__ P, const float* __restrict__ F, float* __restrict__ Hin){
    int idx = blockIdx.x*256+threadIdx.x;
    float h=0.f;
    for (int c=0;c<NCH;c++){
        size_t o = (size_t)c*(EX*NS) + idx;
        Hin[o]=h;
        h = P[o]*h + F[o];
    }
}

// Phase C: replay with true initial state; emit y = (h.C + D*xc)*silu(z).
__global__ __launch_bounds__(256)
void scanC_k(const float* __restrict__ dt, const float* __restrict__ xc, const float* __restrict__ dbc,
             const float* __restrict__ Alog, const float* __restrict__ Hin,
             const float* __restrict__ Dp, const float* __restrict__ xz, float* __restrict__ y){
    int e = blockIdx.x*256 + threadIdx.x;
    int c = blockIdx.y;
    __shared__ float Bsh[CHUNK][NS];
    __shared__ float Csh[CHUNK][NS];
    for (int idx=threadIdx.x; idx<CHUNK*NS; idx+=256){
        int tt = idx>>4, n = idx&15;
        const float* row = dbc + (size_t)(c*CHUNK+tt)*XPN;
        Bsh[tt][n] = row[DTRR+n];
        Csh[tt][n] = row[DTRR+NS+n];
    }
    __syncthreads();
    float Aa[NS], h[NS];
    size_t hb = ((size_t)c*EX+e)*NS;
#pragma unroll
    for (int n=0;n<NS;n++){ Aa[n]=-__expf(Alog[(size_t)e*NS+n]); h[n]=Hin[hb+n]; }
    float Dv = Dp[e];
    int t0=c*CHUNK;
    for (int tt=0;tt<CHUNK;tt++){
        int t=t0+tt;
        float dtv = dt[(size_t)t*EX+e];
        float xcv = xc[(size_t)t*EX+e];
        float du = dtv*xcv;
        float acc=0.f;
#pragma unroll
        for (int n=0;n<NS;n++){
            float dA=__expf(dtv*Aa[n]);
            h[n]=dA*h[n]+du*Bsh[tt][n];
            acc += h[n]*Csh[tt][n];
        }
        float z = xz[(size_t)t*(2*EX) + EX + e];
        y[(size_t)t*EX+e] = (acc + Dv*xcv)*silu_f(z);
    }
}

// ---------------- orchestration ----------------
extern "C" void kernel_launch(void* const* d_in, const int* in_sizes, int n_in,
                              void* d_out, int out_size) {
    const int*   ids  = (const int*)d_in[0];
    const float* emb  = (const float*)d_in[1];
    const float* inw  = (const float*)d_in[2];
    const float* cw   = (const float*)d_in[3];
    const float* cb   = (const float*)d_in[4];
    const float* xpw  = (const float*)d_in[5];
    const float* dtw  = (const float*)d_in[6];
    const float* dtb  = (const float*)d_in[7];
    const float* alog = (const float*)d_in[8];
    const float* dpar = (const float*)d_in[9];
    const float* outw = (const float*)d_in[10];
    const float* nw   = (const float*)d_in[11];
    const float* nfw  = (const float*)d_in[12];
    const float* hw   = (const float*)d_in[13];
    float* out = (float*)d_out;

    float* base = nullptr;
    cudaGetSymbolAddress((void**)&base, g_scr);
    float* p_res = base+O_RES; float* p_h   = base+O_H;   float* p_x   = base+O_X;
    float* p_xz  = base+O_XZ;  float* p_xc  = base+O_XC;  float* p_dt  = base+O_DT;
    float* p_y   = base+O_Y;   float* p_dbc = base+O_DBC; float* p_P   = base+O_P;
    float* p_F   = base+O_F;   float* p_hin = base+O_HIN; float* p_xpp = base+O_XPP;

    embed_k<<<(L*DIM)/256,256>>>(ids, emb, p_res);

    for (int i=0;i<NL;i++){
        // residual add (skipped layer 0) + rmsnorm -> h
        addnorm_k<<<L,256>>>(p_res, p_x, nw + (size_t)i*DIM, p_h, i>0);
        // xz = h @ in_proj^T   (2048 x 4096 x 1024)
        gemm_tn<0><<<dim3(L/128, (2*EX)/128, 1),256>>>(p_h, DIM, inw + (size_t)i*2*EX*DIM, DIM,
                                                       p_xz, 2*EX, 0, 2*EX, DIM, nullptr);
        // causal depthwise conv + silu on x-half of xz -> xc
        conv_silu_k<<<(L*EX)/256,256>>>(p_xz, cw + (size_t)i*EX*KC, cb + (size_t)i*EX, p_xc);
        // dbc = xc @ x_proj^T  (2048 x 96 x 2048), split-K into partials, then reduce
        gemm_tn<0><<<dim3(L/128, 1, SPLITS),256>>>(p_xc, EX, xpw + (size_t)i*XPN*EX, EX,
                                                   p_xpp, XPN, SZ_DBC, XPN, EX/SPLITS, nullptr);
        reduce16_k<<<SZ_DBC/256,256>>>(p_xpp, p_dbc);
        // dt = softplus(dbc[:, :64] @ dt_proj^T + dt_b)  (2048 x 2048 x 64)
        gemm_tn<2><<<dim3(L/128, EX/128, 1),256>>>(p_dbc, XPN, dtw + (size_t)i*EX*DTRR, DTRR,
                                                   p_dt, EX, 0, EX, DTRR, dtb + (size_t)i*EX);
        // chunked selective scan + z-gating -> y
        scanA_k<<<dim3(EX/256, NCH),256>>>(p_dt, p_xc, p_dbc, alog + (size_t)i*EX*NS, p_P, p_F);
        scanB_k<<<(EX*NS)/256,256>>>(p_P, p_F, p_hin);
        scanC_k<<<dim3(EX/256, NCH),256>>>(p_dt, p_xc, p_dbc, alog + (size_t)i*EX*NS,
                                           p_hin, dpar + (size_t)i*EX, p_xz, p_y);
        // x = y @ out_proj^T   (2048 x 1024 x 2048)
        gemm_tn<0><<<dim3(L/128, DIM/128, 1),256>>>(p_y, EX, outw + (size_t)i*DIM*EX, EX,
                                                    p_x, DIM, 0, DIM, EX, nullptr);
    }

    // final residual + rmsnorm, then LM head (2048 x 50257 x 1024)
    addnorm_k<<<L,256>>>(p_res, p_x, nfw, p_h, 1);
    gemm_tn<0><<<dim3(L/128, (VOCAB+127)/128, 1),256>>>(p_h, DIM, hw, DIM,
                                                        out, VOCAB, 0, VOCAB, DIM, nullptr);
}

// round 13
// speedup vs baseline: 2.4728x; 2.4685x over previous
#include <cuda_runtime.h>
#include <cuda_bf16.h>
#include <math.h>
#include <cstdint>

#define L 2048
#define DIM 1024
#define NL 12
#define EX 2048
#define NS 16
#define DTRR 64
#define KC 4
#define VOCAB 50257
#define CHUNK 64
#define NCH 32
#define XPN 96
#define XPS 8          // split-K factor for x_proj

__device__ __forceinline__ float silu_f(float x){ return x/(1.f+__expf(-x)); }
__device__ __forceinline__ float softplus_f(float x){ return fmaxf(x,0.f)+log1pf(__expf(-fabsf(x))); }

__device__ __forceinline__ uint32_t smem_to_u32(const void* p){
    uint32_t a; asm("{ .reg .u64 t; cvta.to.shared.u64 t, %1; cvt.u32.u64 %0, t; }" : "=r"(a) : "l"(p));
    return a;
}
__device__ __forceinline__ void cp16(uint32_t dst, const void* src, int sz){
    asm volatile("cp.async.cg.shared.global [%0], [%1], 16, %2;" :: "r"(dst), "l"(src), "r"(sz));
}
#define CP_COMMIT() asm volatile("cp.async.commit_group;" ::: "memory")
#define CP_WAIT1()  asm volatile("cp.async.wait_group 1;" ::: "memory")

#define LDSM4(R, addr) \
  asm volatile("ldmatrix.sync.aligned.m8n8.x4.shared.b16 {%0,%1,%2,%3}, [%4];" \
    : "=r"((R)[0]),"=r"((R)[1]),"=r"((R)[2]),"=r"((R)[3]) : "r"(addr))

#define MMA(D, A, b0_, b1_) \
  asm volatile("mma.sync.aligned.m16n8k16.row.col.f32.bf16.bf16.f32 " \
    "{%0,%1,%2,%3}, {%4,%5,%6,%7}, {%8,%9}, {%0,%1,%2,%3};" \
    : "+f"((D)[0]),"+f"((D)[1]),"+f"((D)[2]),"+f"((D)[3]) \
    : "r"((A)[0]),"r"((A)[1]),"r"((A)[2]),"r"((A)[3]), "r"(b0_),"r"(b1_))

// ===================== scratch (static device memory) =====================
#define SZ_MAT (L*DIM)
#define SZ_XZ  (L*2*EX)
#define SZ_E   (L*EX)
#define SZ_DBC (L*XPN)
#define SZ_PF  (NCH*EX*NS)

#define O_RES 0
#define O_H   (O_RES+SZ_MAT)
#define O_X   (O_H+SZ_MAT)
#define O_XZ  (O_X+SZ_MAT)
#define O_XC  (O_XZ+SZ_XZ)
#define O_DT  (O_XC+SZ_E)
#define O_Y   (O_DT+SZ_E)
#define O_DBC (O_Y+SZ_E)
#define O_P   (O_DBC+SZ_DBC)
#define O_F   (O_P+SZ_PF)
#define O_HIN (O_F+SZ_PF)
#define O_XPP (O_HIN+SZ_PF)
#define SCRATCH_TOTAL (O_XPP + XPS*SZ_DBC)

__device__ __align__(256) float g_scr[SCRATCH_TOTAL];

// hi/lo bf16 split buffers (weights sized for LM head = the largest)
#define W_MAX (VOCAB*DIM)
__device__ __align__(256) __nv_bfloat16 g_whi[W_MAX];
__device__ __align__(256) __nv_bfloat16 g_wlo[W_MAX];
__device__ __align__(256) __nv_bfloat16 g_ahi[L*EX];
__device__ __align__(256) __nv_bfloat16 g_alo[L*EX];

// ===================== fp32 -> (hi,lo) bf16 split =====================
__global__ void cvt_split_k(const float* __restrict__ src, __nv_bfloat16* __restrict__ hi,
                            __nv_bfloat16* __restrict__ lo, int n4){
    int i = blockIdx.x*256 + threadIdx.x;
    if (i >= n4) return;
    float4 v = ((const float4*)src)[i];
    __nv_bfloat16 h0=__float2bfloat16_rn(v.x), h1=__float2bfloat16_rn(v.y);
    __nv_bfloat16 h2=__float2bfloat16_rn(v.z), h3=__float2bfloat16_rn(v.w);
    __nv_bfloat16 l0=__float2bfloat16_rn(v.x-__bfloat162float(h0));
    __nv_bfloat16 l1=__float2bfloat16_rn(v.y-__bfloat162float(h1));
    __nv_bfloat16 l2=__float2bfloat16_rn(v.z-__bfloat162float(h2));
    __nv_bfloat16 l3=__float2bfloat16_rn(v.w-__bfloat162float(h3));
    ((__nv_bfloat162*)hi)[2*i  ] = __nv_bfloat162(h0,h1);
    ((__nv_bfloat162*)hi)[2*i+1] = __nv_bfloat162(h2,h3);
    ((__nv_bfloat162*)lo)[2*i  ] = __nv_bfloat162(l0,l1);
    ((__nv_bfloat162*)lo)[2*i+1] = __nv_bfloat162(l2,l3);
}

// ===================== mma.sync bf16x3 GEMM: C[M,N] = A[M,K] * B[N,K]^T =====================
// 128x128 CTA tile, BK=32, 3-stage cp.async pipeline, 8 warps (4m x 2n),
// warp tile 32x64. bf16x3: acc += Ah*Bh + Ah*Bl + Al*Bh.
// Smem stage layout (32KB): Ahi[8K] Alo[8K] Bhi[8K] Blo[8K].
// Row = 64B (32 bf16), swizzle: 16B-chunk kc stored at kc ^ ((row>>1)&3).
#define STAGE_BYTES 32768
#define MM_SMEM (3*STAGE_BYTES)

__device__ __forceinline__ void ldgsts_stage(uint32_t sstage,
    const __nv_bfloat16* __restrict__ Ahi, const __nv_bfloat16* __restrict__ Alo, int lda,
    const __nv_bfloat16* __restrict__ Bhi, const __nv_bfloat16* __restrict__ Blo, int ldb,
    int bm, int bn, int N, int ktg, int tid)
{
#pragma unroll
    for (int j=0;j<2;j++){
        int ci = tid + j*256;
        int row = ci>>2, kc = ci&3;
        uint32_t dst = sstage + (uint32_t)(row*64 + ((kc ^ ((row>>1)&3))<<4));
        size_t aoff = (size_t)(bm+row)*lda + ktg + kc*8;
        cp16(dst,         Ahi + aoff, 16);
        cp16(dst + 8192,  Alo + aoff, 16);
        int brow = bn + row;
        int ok = (brow < N) ? 16 : 0;
        size_t boff = (size_t)(ok ? brow : bn)*ldb + ktg + kc*8;
        cp16(dst + 16384, Bhi + boff, ok);
        cp16(dst + 24576, Blo + boff, ok);
    }
}

template<int EPI>
__global__ __launch_bounds__(256,2)
void mm_gemm(const __nv_bfloat16* __restrict__ Ahi, const __nv_bfloat16* __restrict__ Alo, int lda,
             const __nv_bfloat16* __restrict__ Bhi, const __nv_bfloat16* __restrict__ Blo, int ldb,
             float* __restrict__ C, int ldc, int partStride, int N, int kLen,
             const float* __restrict__ bias)
{
    extern __shared__ char smem[];
    const uint32_t sb = smem_to_u32(smem);
    const int tid = threadIdx.x, lane = tid&31, wid = tid>>5;
    const int wm = wid&3, wn = wid>>2;
    const int bm = blockIdx.x*128, bn = blockIdx.y*128;
    const int k0 = blockIdx.z*kLen;
    const int ktiles = kLen/32;

    // prefetch stages 0,1 (ktiles >= 2 for all call sites)
    ldgsts_stage(sb,             Ahi,Alo,lda, Bhi,Blo,ldb, bm,bn,N, k0,      tid); CP_COMMIT();
    ldgsts_stage(sb+STAGE_BYTES, Ahi,Alo,lda, Bhi,Blo,ldb, bm,bn,N, k0+32,   tid); CP_COMMIT();

    float acc[2][8][4];
#pragma unroll
    for (int a=0;a<2;a++)
#pragma unroll
        for (int b=0;b<8;b++)
#pragma unroll
            for (int c=0;c<4;c++) acc[a][b][c]=0.f;

    const int a_row_l = (lane&15);
    const int kc_l    = (lane>>4);

    for (int i=0;i<ktiles;i++){
        CP_WAIT1();
        __syncthreads();
        if (i+2 < ktiles)
            ldgsts_stage(sb + ((i+2)%3)*STAGE_BYTES, Ahi,Alo,lda, Bhi,Blo,ldb,
                         bm,bn,N, k0+(i+2)*32, tid);
        CP_COMMIT();

        uint32_t base = sb + (i%3)*STAGE_BYTES;
#pragma unroll
        for (int ks=0; ks<2; ks++){
            const int kc = ks*2 + kc_l;
            uint32_t ah[2][4], al[2][4];
#pragma unroll
            for (int mf=0; mf<2; mf++){
                int row = wm*32 + mf*16 + a_row_l;
                uint32_t ad = base + (uint32_t)(row*64 + ((kc ^ ((row>>1)&3))<<4));
                LDSM4(ah[mf], ad);
                LDSM4(al[mf], ad + 8192);
            }
#pragma unroll
            for (int nf16=0; nf16<4; nf16++){
                int row = wn*64 + nf16*16 + a_row_l;
                uint32_t bd = base + 16384u + (uint32_t)(row*64 + ((kc ^ ((row>>1)&3))<<4));
                uint32_t bh[4], bl[4];
                LDSM4(bh, bd);
                LDSM4(bl, bd + 8192);
#pragma unroll
                for (int mf=0; mf<2; mf++){
#pragma unroll
                    for (int hh=0; hh<2; hh++){
                        const int nf = nf16*2 + hh;
                        MMA(acc[mf][nf], ah[mf], bh[hh], bh[2+hh]);
                        MMA(acc[mf][nf], ah[mf], bl[hh], bl[2+hh]);
                        MMA(acc[mf][nf], al[mf], bh[hh], bh[2+hh]);
                    }
                }
            }
        }
    }

    // epilogue: acc -> C (rows lane>>2 / +8, cols (lane&3)*2 / +1)
    float* Cz = C + (size_t)blockIdx.z*partStride;
    const bool even = ((ldc & 1) == 0);
#pragma unroll
    for (int mf=0; mf<2; mf++){
#pragma unroll
        for (int nf=0; nf<8; nf++){
            int rr = bm + wm*32 + mf*16 + (lane>>2);
            int cc = bn + wn*64 + nf*8 + ((lane&3)<<1);
#pragma unroll
            for (int h=0; h<2; h++){
                int r = rr + h*8;
                float v0 = acc[mf][nf][h*2+0];
                float v1 = acc[mf][nf][h*2+1];
                if (EPI==1){ v0 = softplus_f(v0+bias[cc]); v1 = softplus_f(v1+bias[cc+1]); }
                float* p = Cz + (size_t)r*ldc + cc;
                if (cc+1 < N){
                    if (even) *(float2*)p = make_float2(v0,v1);
                    else { p[0]=v0; p[1]=v1; }
                } else if (cc < N) p[0]=v0;
            }
        }
    }
}

// ===================== embedding gather =====================
__global__ void embed_k(const int* __restrict__ ids, const float* __restrict__ emb, float* __restrict__ res){
    int i = blockIdx.x*256 + threadIdx.x;
    int l = i >> 10;
    res[i] = emb[(size_t)ids[l]*DIM + (i & (DIM-1))];
}

// ===================== residual add + RMSNorm =====================
__global__ void addnorm_k(float* __restrict__ res, const float* __restrict__ xin,
                          const float* __restrict__ w, float* __restrict__ hout, int addX){
    int r = blockIdx.x;
    float* rr = res + (size_t)r*DIM;
    const float* xr = xin + (size_t)r*DIM;
    float v[4]; float s=0.f;
#pragma unroll
    for (int q=0;q<4;q++){
        int j = threadIdx.x + q*256;
        float val = rr[j];
        if (addX){ val += xr[j]; rr[j]=val; }
        v[q]=val; s += val*val;
    }
#pragma unroll
    for (int o=16;o>0;o>>=1) s += __shfl_xor_sync(0xffffffffu, s, o);
    __shared__ float red[8];
    if ((threadIdx.x&31)==0) red[threadIdx.x>>5]=s;
    __syncthreads();
    if (threadIdx.x<32){
        float t = (threadIdx.x<8)?red[threadIdx.x]:0.f;
#pragma unroll
        for (int o=4;o>0;o>>=1) t += __shfl_xor_sync(0xffffffffu,t,o);
        if (threadIdx.x==0) red[0] = rsqrtf(t/(float)DIM + 1e-5f);
    }
    __syncthreads();
    float inv = red[0];
#pragma unroll
    for (int q=0;q<4;q++){
        int j = threadIdx.x + q*256;
        hout[(size_t)r*DIM+j] = v[q]*inv*w[j];
    }
}

// ===================== causal depthwise conv (K=4) + SiLU =====================
__global__ void conv_silu_k(const float* __restrict__ xz, const float* __restrict__ cw,
                            const float* __restrict__ cb, float* __restrict__ xc){
    int i = blockIdx.x*256+threadIdx.x;   // i = l*EX + e
    int e = i & (EX-1);
    int l = i >> 11;
    float4 w = *(const float4*)(cw + e*4);
    const float* col = xz + e;
    float s = cb[e] + w.w*col[(size_t)l*(2*EX)];
    if (l>=1) s += w.z*col[(size_t)(l-1)*(2*EX)];
    if (l>=2) s += w.y*col[(size_t)(l-2)*(2*EX)];
    if (l>=3) s += w.x*col[(size_t)(l-3)*(2*EX)];
    xc[i] = silu_f(s);
}

// ===================== split-K reduction for x_proj partials =====================
__global__ void reduce8_k(const float* __restrict__ part, float* __restrict__ outp){
    int i = blockIdx.x*256+threadIdx.x;
    float s=0.f;
#pragma unroll
    for (int z=0;z<XPS;z++) s += part[(size_t)z*SZ_DBC + i];
    outp[i]=s;
}

// ===================== selective scan: chunked 3-phase =====================
__global__ __launch_bounds__(256)
void scanA_k(const float* __restrict__ dt, const float* __restrict__ xc, const float* __restrict__ dbc,
             const float* __restrict__ Alog, float* __restrict__ P, float* __restrict__ F){
    int e = blockIdx.x*256 + threadIdx.x;
    int c = blockIdx.y;
    __shared__ float Bsh[CHUNK][NS];
    for (int idx=threadIdx.x; idx<CHUNK*NS; idx+=256){
        int tt = idx>>4, n = idx&15;
        Bsh[tt][n] = dbc[(size_t)(c*CHUNK+tt)*XPN + DTRR + n];
    }
    __syncthreads();
    float Aa[NS], h[NS], p[NS];
#pragma unroll
    for (int n=0;n<NS;n++){ Aa[n] = -__expf(Alog[(size_t)e*NS+n]); h[n]=0.f; p[n]=1.f; }
    int t0=c*CHUNK;
    for (int tt=0;tt<CHUNK;tt++){
        int t=t0+tt;
        float dtv = dt[(size_t)t*EX+e];
        float du  = dtv*xc[(size_t)t*EX+e];
#pragma unroll
        for (int n=0;n<NS;n++){
            float dA = __expf(dtv*Aa[n]);
            h[n] = dA*h[n] + du*Bsh[tt][n];
            p[n]*= dA;
        }
    }
    size_t bse = ((size_t)c*EX + e)*NS;
#pragma unroll
    for (int n=0;n<NS;n++){ P[bse+n]=p[n]; F[bse+n]=h[n]; }
}

__global__ void scanB_k(const float* __restrict__ P, const float* __restrict__ F, float* __restrict__ Hin){
    int idx = blockIdx.x*256+threadIdx.x;
    float h=0.f;
    for (int c=0;c<NCH;c++){
        size_t o = (size_t)c*(EX*NS) + idx;
        Hin[o]=h;
        h = P[o]*h + F[o];
    }
}

__global__ __launch_bounds__(256)
void scanC_k(const float* __restrict__ dt, const float* __restrict__ xc, const float* __restrict__ dbc,
             const float* __restrict__ Alog, const float* __restrict__ Hin,
             const float* __restrict__ Dp, const float* __restrict__ xz, float* __restrict__ y){
    int e = blockIdx.x*256 + threadIdx.x;
    int c = blockIdx.y;
    __shared__ float Bsh[CHUNK][NS];
    __shared__ float Csh[CHUNK][NS];
    for (int idx=threadIdx.x; idx<CHUNK*NS; idx+=256){
        int tt = idx>>4, n = idx&15;
        const float* row = dbc + (size_t)(c*CHUNK+tt)*XPN;
        Bsh[tt][n] = row[DTRR+n];
        Csh[tt][n] = row[DTRR+NS+n];
    }
    __syncthreads();
    float Aa[NS], h[NS];
    size_t hb = ((size_t)c*EX+e)*NS;
#pragma unroll
    for (int n=0;n<NS;n++){ Aa[n]=-__expf(Alog[(size_t)e*NS+n]); h[n]=Hin[hb+n]; }
    float Dv = Dp[e];
    int t0=c*CHUNK;
    for (int tt=0;tt<CHUNK;tt++){
        int t=t0+tt;
        float dtv = dt[(size_t)t*EX+e];
        float xcv = xc[(size_t)t*EX+e];
        float du = dtv*xcv;
        float acc=0.f;
#pragma unroll
        for (int n=0;n<NS;n++){
            float dA=__expf(dtv*Aa[n]);
            h[n]=dA*h[n]+du*Bsh[tt][n];
            acc += h[n]*Csh[tt][n];
        }
        float z = xz[(size_t)t*(2*EX) + EX + e];
        y[(size_t)t*EX+e] = (acc + Dv*xcv)*silu_f(z);
    }
}

// ===================== orchestration =====================
static inline void cvt(const float* src, __nv_bfloat16* hi, __nv_bfloat16* lo, int n){
    int n4 = n >> 2;
    cvt_split_k<<<(n4+255)/256,256>>>(src, hi, lo, n4);
}

extern "C" void kernel_launch(void* const* d_in, const int* in_sizes, int n_in,
                              void* d_out, int out_size) {
    const int*   ids  = (const int*)d_in[0];
    const float* emb  = (const float*)d_in[1];
    const float* inw  = (const float*)d_in[2];
    const float* cw   = (const float*)d_in[3];
    const float* cb   = (const float*)d_in[4];
    const float* xpw  = (const float*)d_in[5];
    const float* dtw  = (const float*)d_in[6];
    const float* dtb  = (const float*)d_in[7];
    const float* alog = (const float*)d_in[8];
    const float* dpar = (const float*)d_in[9];
    const float* outw = (const float*)d_in[10];
    const float* nw   = (const float*)d_in[11];
    const float* nfw  = (const float*)d_in[12];
    const float* hw   = (const float*)d_in[13];
    float* out = (float*)d_out;

    cudaFuncSetAttribute(mm_gemm<0>, cudaFuncAttributeMaxDynamicSharedMemorySize, MM_SMEM);
    cudaFuncSetAttribute(mm_gemm<1>, cudaFuncAttributeMaxDynamicSharedMemorySize, MM_SMEM);

    float* base = nullptr;
    cudaGetSymbolAddress((void**)&base, g_scr);
    float* p_res = base+O_RES; float* p_h   = base+O_H;   float* p_x   = base+O_X;
    float* p_xz  = base+O_XZ;  float* p_xc  = base+O_XC;  float* p_dt  = base+O_DT;
    float* p_y   = base+O_Y;   float* p_dbc = base+O_DBC; float* p_xpp = base+O_XPP;
    float* p_P   = base+O_P;   float* p_F   = base+O_F;   float* p_hin = base+O_HIN;

    __nv_bfloat16 *whi=nullptr,*wlo=nullptr,*ahi=nullptr,*alo=nullptr;
    cudaGetSymbolAddress((void**)&whi, g_whi);
    cudaGetSymbolAddress((void**)&wlo, g_wlo);
    cudaGetSymbolAddress((void**)&ahi, g_ahi);
    cudaGetSymbolAddress((void**)&alo, g_alo);

    embed_k<<<(L*DIM)/256,256>>>(ids, emb, p_res);

    for (int i=0;i<NL;i++){
        // residual add (skipped layer 0) + rmsnorm -> h
        addnorm_k<<<L,256>>>(p_res, p_x, nw + (size_t)i*DIM, p_h, i>0);
        // xz = h @ in_proj^T   (2048 x 4096 x 1024)
        cvt(p_h, ahi, alo, L*DIM);
        cvt(inw + (size_t)i*2*EX*DIM, whi, wlo, 2*EX*DIM);
        mm_gemm<0><<<dim3(L/128,(2*EX)/128,1),256,MM_SMEM>>>(ahi, alo, DIM, whi, wlo, DIM,
                                                             p_xz, 2*EX, 0, 2*EX, DIM, nullptr);
        // causal depthwise conv + silu -> xc
        conv_silu_k<<<(L*EX)/256,256>>>(p_xz, cw + (size_t)i*EX*KC, cb + (size_t)i*EX, p_xc);
        // dbc = xc @ x_proj^T  (2048 x 96 x 2048), split-K x8 + reduce
        cvt(p_xc, ahi, alo, L*EX);
        cvt(xpw + (size_t)i*XPN*EX, whi, wlo, XPN*EX);
        mm_gemm<0><<<dim3(L/128,1,XPS),256,MM_SMEM>>>(ahi, alo, EX, whi, wlo, EX,
                                                      p_xpp, XPN, SZ_DBC, XPN, EX/XPS, nullptr);
        reduce8_k<<<SZ_DBC/256,256>>>(p_xpp, p_dbc);
        // dt = softplus(dbc[:, :64] @ dt_proj^T + dt_b)  (2048 x 2048 x 64)
        cvt(p_dbc, ahi, alo, L*XPN);
        cvt(dtw + (size_t)i*EX*DTRR, whi, wlo, EX*DTRR);
        mm_gemm<1><<<dim3(L/128,EX/128,1),256,MM_SMEM>>>(ahi, alo, XPN, whi, wlo, DTRR,
                                                         p_dt, EX, 0, EX, DTRR, dtb + (size_t)i*EX);
        // chunked selective scan + z-gating -> y
        scanA_k<<<dim3(EX/256,NCH),256>>>(p_dt, p_xc, p_dbc, alog + (size_t)i*EX*NS, p_P, p_F);
        scanB_k<<<(EX*NS)/256,256>>>(p_P, p_F, p_hin);
        scanC_k<<<dim3(EX/256,NCH),256>>>(p_dt, p_xc, p_dbc, alog + (size_t)i*EX*NS,
                                          p_hin, dpar + (size_t)i*EX, p_xz, p_y);
        // x = y @ out_proj^T   (2048 x 1024 x 2048)
        cvt(p_y, ahi, alo, L*EX);
        cvt(outw + (size_t)i*DIM*EX, whi, wlo, DIM*EX);
        mm_gemm<0><<<dim3(L/128,DIM/128,1),256,MM_SMEM>>>(ahi, alo, EX, whi, wlo, EX,
                                                          p_x, DIM, 0, DIM, EX, nullptr);
    }

    // final residual + rmsnorm, then LM head (2048 x 50257 x 1024)
    addnorm_k<<<L,256>>>(p_res, p_x, nfw, p_h, 1);
    cvt(p_h, ahi, alo, L*DIM);
    cvt(hw, whi, wlo, VOCAB*DIM);
    mm_gemm<0><<<dim3(L/128,(VOCAB+127)/128,1),256,MM_SMEM>>>(ahi, alo, DIM, whi, wlo, DIM,
                                                              out, VOCAB, 0, VOCAB, DIM, nullptr);
}